// round 10
// baseline (speedup 1.0000x reference)
#include <cuda_runtime.h>
#include <cuda_bf16.h>
#include <math.h>

#define DD 128           // feature dim
#define HH 16            // hidden dim
#define MAXN 131072      // >= N=100000

// Scratch for per-node projections (no cudaMalloc allowed)
__device__ float g_U[(size_t)MAXN * HH];
__device__ float g_V[(size_t)MAXN * HH];

// Stream/events for fork-join overlap (created once at load; not device memory)
static cudaStream_t g_s2 = nullptr;
static cudaEvent_t g_evFork = nullptr, g_evJoin = nullptr;
static const bool g_init = [](){
    cudaStreamCreate(&g_s2);
    cudaEventCreateWithFlags(&g_evFork, cudaEventDisableTiming);
    cudaEventCreateWithFlags(&g_evJoin, cudaEventDisableTiming);
    return true;
}();

__device__ __forceinline__ unsigned long long fma_f32x2(
    unsigned long long a, unsigned long long b, unsigned long long c)
{
    unsigned long long d;
    asm("fma.rn.f32x2 %0, %1, %2, %3;" : "=l"(d) : "l"(a), "l"(b), "l"(c));
    return d;
}

// ---------------------------------------------------------------------------
// Kernel 1: U[n] = z[n] @ W1[0:128] + b1 ; V[n] = z[n] @ W1[128:256]
// z staged through smem in coalesced 256x32 chunks (1 line per warp-instr),
// read back conflict-free (pad-33). Packed f32x2 FMA (2 MACs/instr).
// ---------------------------------------------------------------------------
__global__ __launch_bounds__(256) void proj_kernel(
    const float* __restrict__ z, const float* __restrict__ W1,
    const float* __restrict__ b1, int N)
{
    __shared__ float sWf[2 * DD * HH];       // 16 KB weights
    __shared__ float sb[HH];
    __shared__ float sZ[256 * 33];           // 33 KB z chunk (pad 33)

    {
        const float4* src = reinterpret_cast<const float4*>(W1);
        float4* dst = reinterpret_cast<float4*>(sWf);
        for (int i = threadIdx.x; i < (2 * DD * HH) / 4; i += blockDim.x) dst[i] = src[i];
        if (threadIdx.x < HH) sb[threadIdx.x] = b1[threadIdx.x];
    }
    __syncthreads();

    const int tid = threadIdx.x;
    const int n_base = blockIdx.x * 256;
    const int n = n_base + tid;

    // accumulators as packed f32x2 (8 pairs each for u and v)
    unsigned long long u2[HH / 2], v2[HH / 2];
#pragma unroll
    for (int j = 0; j < HH / 2; j++) {
        asm("mov.b64 %0, {%1, %2};" : "=l"(u2[j]) : "f"(sb[2 * j]), "f"(sb[2 * j + 1]));
        asm("mov.b64 %0, {%1, %2};" : "=l"(v2[j]) : "f"(0.0f), "f"(0.0f));
    }

    const ulonglong2* sW2 = reinterpret_cast<const ulonglong2*>(sWf);
    const bool full_tile = (n_base + 256 <= N);

#pragma unroll 1
    for (int kc = 0; kc < 4; kc++) {
        if (kc) __syncthreads();   // previous chunk's readers done
        // Stage 256 nodes x 32 k-values; each warp-iteration reads ONE 128B line.
        if (full_tile) {
#pragma unroll
            for (int i = 0; i < 32; i++) {
                int idx = tid + i * 256;            // 0..8191
                int r = idx >> 5, c = idx & 31;
                sZ[r * 33 + c] = z[(size_t)(n_base + r) * DD + kc * 32 + c];
            }
        } else {
#pragma unroll
            for (int i = 0; i < 32; i++) {
                int idx = tid + i * 256;
                int r = idx >> 5, c = idx & 31;
                int nn = n_base + r;
                sZ[r * 33 + c] = (nn < N) ? z[(size_t)nn * DD + kc * 32 + c] : 0.0f;
            }
        }
        __syncthreads();

        const float* myz = &sZ[tid * 33];
#pragma unroll
        for (int kk = 0; kk < 32; kk++) {
            int k = kc * 32 + kk;
            float zk = myz[kk];
            unsigned long long zk2;
            asm("mov.b64 %0, {%1, %1};" : "=l"(zk2) : "f"(zk));
            const ulonglong2* wu = sW2 + (size_t)k * (HH / 4);
            const ulonglong2* wv = sW2 + (size_t)(DD + k) * (HH / 4);
#pragma unroll
            for (int j = 0; j < HH / 4; j++) {
                ulonglong2 a = wu[j];
                u2[2 * j]     = fma_f32x2(zk2, a.x, u2[2 * j]);
                u2[2 * j + 1] = fma_f32x2(zk2, a.y, u2[2 * j + 1]);
                ulonglong2 b = wv[j];
                v2[2 * j]     = fma_f32x2(zk2, b.x, v2[2 * j]);
                v2[2 * j + 1] = fma_f32x2(zk2, b.y, v2[2 * j + 1]);
            }
        }
    }

    if (n < N) {
        ulonglong2* Up = reinterpret_cast<ulonglong2*>(&g_U[(size_t)n * HH]);
        ulonglong2* Vp = reinterpret_cast<ulonglong2*>(&g_V[(size_t)n * HH]);
#pragma unroll
        for (int j = 0; j < HH / 4; j++) {
            Up[j] = make_ulonglong2(u2[2 * j], u2[2 * j + 1]);
            Vp[j] = make_ulonglong2(v2[2 * j], v2[2 * j + 1]);
        }
    }
}

// ---------------------------------------------------------------------------
// Kernel A (independent of proj): adj[e] = dot(z[row], z[col]).
// 4 edges per warp, 8 lanes per edge. L2-bandwidth bound.
// ---------------------------------------------------------------------------
__global__ __launch_bounds__(256) void adj_kernel(
    const float* __restrict__ z, const int* __restrict__ ei,
    float* __restrict__ out, int E)
{
    int tid  = blockIdx.x * blockDim.x + threadIdx.x;
    int warp = tid >> 5;
    int lane = threadIdx.x & 31;
    int sub  = lane >> 3;       // which of 4 edges this lane serves
    int sl   = lane & 7;        // lane within the 8-lane group

    int e = warp * 4 + sub;
    if (e >= E) return;

    int r = __ldg(&ei[e]);
    int c = __ldg(&ei[(size_t)E + e]);

    const float4* zr4 = reinterpret_cast<const float4*>(z) + (size_t)r * (DD / 4);
    const float4* zc4 = reinterpret_cast<const float4*>(z) + (size_t)c * (DD / 4);
    float4 a0 = __ldg(&zr4[sl]);
    float4 a1 = __ldg(&zr4[sl + 8]);
    float4 a2 = __ldg(&zr4[sl + 16]);
    float4 a3 = __ldg(&zr4[sl + 24]);
    float4 b0 = __ldg(&zc4[sl]);
    float4 b1v = __ldg(&zc4[sl + 8]);
    float4 b2v = __ldg(&zc4[sl + 16]);
    float4 b3 = __ldg(&zc4[sl + 24]);

    float p = a0.x * b0.x;
    p = fmaf(a0.y, b0.y, p);  p = fmaf(a0.z, b0.z, p);  p = fmaf(a0.w, b0.w, p);
    p = fmaf(a1.x, b1v.x, p); p = fmaf(a1.y, b1v.y, p);
    p = fmaf(a1.z, b1v.z, p); p = fmaf(a1.w, b1v.w, p);
    p = fmaf(a2.x, b2v.x, p); p = fmaf(a2.y, b2v.y, p);
    p = fmaf(a2.z, b2v.z, p); p = fmaf(a2.w, b2v.w, p);
    p = fmaf(a3.x, b3.x, p);  p = fmaf(a3.y, b3.y, p);
    p = fmaf(a3.z, b3.z, p);  p = fmaf(a3.w, b3.w, p);

#pragma unroll
    for (int off = 4; off > 0; off >>= 1)
        p += __shfl_xor_sync(0xffffffffu, p, off);

    if (sl == 0) out[e] = p;
}

// ---------------------------------------------------------------------------
// Kernel B (after proj): weight[e] = softplus(relu(U[row]+V[col]) @ W2 + b2).
// 8 edges per warp, 4 lanes per edge; each lane owns 4 hidden units (1 float4
// of U and V) -> one 128B line per row, 2 wavefronts/edge.
// ---------------------------------------------------------------------------
__global__ __launch_bounds__(256) void weight_kernel(
    const int* __restrict__ ei, const float* __restrict__ W2,
    const float* __restrict__ b2, float* __restrict__ out, int E)
{
    int tid  = blockIdx.x * blockDim.x + threadIdx.x;
    int warp = tid >> 5;
    int lane = threadIdx.x & 31;
    int sub  = lane >> 2;       // which of 8 edges
    int sl   = lane & 3;        // lane within 4-lane group

    int e = warp * 8 + sub;
    if (e >= E) return;

    int r = __ldg(&ei[e]);
    int c = __ldg(&ei[(size_t)E + e]);

    float4 uu = *reinterpret_cast<const float4*>(&g_U[(size_t)r * HH + 4 * sl]);
    float4 vv = *reinterpret_cast<const float4*>(&g_V[(size_t)c * HH + 4 * sl]);
    float4 w2 = __ldg(reinterpret_cast<const float4*>(&W2[4 * sl]));

    float q =       fmaxf(uu.x + vv.x, 0.0f) * w2.x;
    q = fmaf(fmaxf(uu.y + vv.y, 0.0f), w2.y, q);
    q = fmaf(fmaxf(uu.z + vv.z, 0.0f), w2.z, q);
    q = fmaf(fmaxf(uu.w + vv.w, 0.0f), w2.w, q);

    q += __shfl_xor_sync(0xffffffffu, q, 1);
    q += __shfl_xor_sync(0xffffffffu, q, 2);

    if (sl == 0) {
        float x = q + __ldg(&b2[0]);
        // stable softplus: max(x,0) + log1p(exp(-|x|))
        out[(size_t)E + e] = fmaxf(x, 0.0f) + log1pf(expf(-fabsf(x)));
    }
}

extern "C" void kernel_launch(void* const* d_in, const int* in_sizes, int n_in,
                              void* d_out, int out_size)
{
    const float* z  = (const float*)d_in[0];
    const int*   ei = (const int*)d_in[1];
    const float* W1 = (const float*)d_in[2];
    const float* b1 = (const float*)d_in[3];
    const float* W2 = (const float*)d_in[4];
    const float* b2 = (const float*)d_in[5];
    float*       out = (float*)d_out;

    int N = in_sizes[0] / DD;       // 100000
    int E = in_sizes[1] / 2;        // 600000

    // Fork: adj_kernel (z-only) runs on g_s2 concurrently with proj chain.
    cudaEventRecord(g_evFork, 0);
    cudaStreamWaitEvent(g_s2, g_evFork, 0);

    {   // stream B: adjacency dots (4 edges/warp)
        int blocks = (E + 31) / 32;
        adj_kernel<<<blocks, 256, 0, g_s2>>>(z, ei, out, E);
    }
    {   // stream A (legacy): projections then MLP weights
        int blocks = (N + 255) / 256;
        proj_kernel<<<blocks, 256>>>(z, W1, b1, N);
        int wblocks = (E + 63) / 64;
        weight_kernel<<<wblocks, 256>>>(ei, W2, b2, out, E);
    }

    // Join
    cudaEventRecord(g_evJoin, g_s2);
    cudaStreamWaitEvent(0, g_evJoin, 0);
}